// round 9
// baseline (speedup 1.0000x reference)
#include <cuda_runtime.h>
#include <math.h>

// Problem shape (fixed): B=8, C=64, T=16, H=64, W=64, text_dim=768
#define NB 8
#define NC 64
#define NT 16
#define HW4 1024         // H*W/4 (float4 / longlong2 units per T-plane)
#define TD 768
#define NBC (NB*NC)      // 512

__device__ __forceinline__ unsigned long long pack2(float v) {
    float2 f = make_float2(v, v);
    return *reinterpret_cast<unsigned long long*>(&f);
}

// ---------------------------------------------------------------------------
// Single fused kernel.  Grid (512, 2); 256 threads; each block does TWO
// 256-column chunks (amortizes the gate prologue 2x) with cross-chunk
// register-level prefetch (half-depth: 4 pairs during matvec, 4 after).
// Prologue: E staged in smem (kills 12/24 gate LDGs), 16 sigmoid gates in the
// chunk-0 DRAM-load shadow, folded even/odd 8x8 matrices.
// Per-chunk math identical to R6:  s=x[j]+x[15-j], d=x[j]-x[15-j];
// u=E s, v=O d;  y[t]=u+v, y[15-t]=u-v.
// ---------------------------------------------------------------------------
__global__ __launch_bounds__(256, 2) void fused_kernel(
    const longlong2* __restrict__ r,    // float4 planes as 2x f32x2
    const float4*    __restrict__ E4,   // (B, 768) as float4
    const float4*    __restrict__ Wf4,  // (C*T, 768) as float4
    const float*     __restrict__ bf,   // (C*T,)
    longlong2*       __restrict__ out)
{
    __shared__ float4 sE4[TD / 4];             // 3 KB: this batch's E row
    __shared__ float sw[NT];
    __shared__ float sD[NT][NT];
    __shared__ unsigned long long sEm[8][8];   // duplicated (m,m) pairs
    __shared__ unsigned long long sOm[8][8];

    const int bc = blockIdx.x;
    const int b  = bc >> 6;
    const int c  = bc & 63;
    const int u0 = blockIdx.y * 512 + threadIdx.x;   // chunk0 col; chunk1 = +256
    const size_t base = (size_t)bc * (NT * HW4);

    // ---- chunk-0 front-batched streaming DRAM loads (MLP=16), pairwise ----
    longlong2 xa[8], xb[8];
    #pragma unroll
    for (int j = 0; j < 8; j++) {
        xa[j] = __ldcs(r + base + (size_t)j * HW4 + u0);
        xb[j] = __ldcs(r + base + (size_t)(15 - j) * HW4 + u0);
    }

    // ---- DCT table + E staging (no deps on the loads) ----
    {
        const int k = threadIdx.x >> 4;
        const int t = threadIdx.x & 15;
        const float sc = (k == 0) ? 0.25f : 0.35355339059327373f; // sqrt(1/16), sqrt(2/16)
        sD[k][t] = cosf(3.14159265358979323846f * ((float)t + 0.5f) * (float)k / 16.0f) * sc;
    }
    if (threadIdx.x < TD / 4)
        sE4[threadIdx.x] = __ldg(E4 + (size_t)b * (TD / 4) + threadIdx.x);
    __syncthreads();

    // ---- gates in the load shadow: 16 groups x 16 lanes, one 768-dot ----
    {
        const int g = threadIdx.x >> 4;
        const int l = threadIdx.x & 15;
        const int j = c * NT + g;
        const float4* wrow = Wf4 + (size_t)j * (TD / 4);
        float s = 0.0f;
        #pragma unroll
        for (int i = 0; i < 12; i++) {
            const float4 wv = __ldg(wrow + l + 16 * i);   // L2-resident after wave 1
            const float4 ev = sE4[l + 16 * i];
            s = fmaf(ev.x, wv.x, s);
            s = fmaf(ev.y, wv.y, s);
            s = fmaf(ev.z, wv.z, s);
            s = fmaf(ev.w, wv.w, s);
        }
        #pragma unroll
        for (int o = 8; o; o >>= 1) s += __shfl_xor_sync(0xffffffffu, s, o);
        if (l == 0) {
            const float z = s + __ldg(bf + j);
            sw[g] = 1.0f / (1.0f + expf(-z));
        }
    }
    __syncthreads();

    // ---- folded matrices E (even k) / O (odd k), 8x8 each ----
    if (threadIdx.x < 128) {
        const int t   = (threadIdx.x >> 3) & 7;
        const int jj  = threadIdx.x & 7;
        const int odd = threadIdx.x >> 6;    // 0 -> Em, 1 -> Om
        float acc = 0.0f;
        #pragma unroll
        for (int m = 0; m < 8; m++) {
            const int k = 2 * m + odd;
            acc = fmaf(sD[k][t] * sw[k], sD[k][jj], acc);
        }
        const unsigned long long p = pack2(acc);
        if (odd) sOm[t][jj] = p; else sEm[t][jj] = p;
    }
    __syncthreads();

    const unsigned long long NEG1 = pack2(-1.0f);
    unsigned long long sl[8], sh[8], dl[8], dh[8];

// fold xa/xb -> sl/sh/dl/dh (x regs die here)
#define FOLD8()                                                                         \
    _Pragma("unroll")                                                                   \
    for (int j = 0; j < 8; j++) {                                                       \
        const unsigned long long al = (unsigned long long)xa[j].x;                      \
        const unsigned long long ah = (unsigned long long)xa[j].y;                      \
        const unsigned long long bl = (unsigned long long)xb[j].x;                      \
        const unsigned long long bh = (unsigned long long)xb[j].y;                      \
        asm("add.rn.f32x2 %0, %1, %2;"     : "=l"(sl[j]) : "l"(al), "l"(bl));           \
        asm("add.rn.f32x2 %0, %1, %2;"     : "=l"(sh[j]) : "l"(ah), "l"(bh));           \
        asm("fma.rn.f32x2 %0, %1, %2, %3;" : "=l"(dl[j]) : "l"(NEG1), "l"(bl), "l"(al));\
        asm("fma.rn.f32x2 %0, %1, %2, %3;" : "=l"(dh[j]) : "l"(NEG1), "l"(bh), "l"(ah));\
    }

// u = Em[t]·s, v = Om[t]·d; y[t]=u+v, y[15-t]=u-v; streamed stores at column uu
#define MATVEC_STORE(uu)                                                                \
    _Pragma("unroll")                                                                   \
    for (int t = 0; t < 8; t++) {                                                       \
        unsigned long long ul = 0ull, uh = 0ull, vl = 0ull, vh = 0ull;                  \
        _Pragma("unroll")                                                               \
        for (int j2 = 0; j2 < 4; j2++) {                                                \
            const ulonglong2 e = *(const ulonglong2*)&sEm[t][2 * j2];                   \
            const ulonglong2 o = *(const ulonglong2*)&sOm[t][2 * j2];                   \
            asm("fma.rn.f32x2 %0, %1, %2, %0;" : "+l"(ul) : "l"(e.x), "l"(sl[2*j2  ])); \
            asm("fma.rn.f32x2 %0, %1, %2, %0;" : "+l"(uh) : "l"(e.x), "l"(sh[2*j2  ])); \
            asm("fma.rn.f32x2 %0, %1, %2, %0;" : "+l"(ul) : "l"(e.y), "l"(sl[2*j2+1])); \
            asm("fma.rn.f32x2 %0, %1, %2, %0;" : "+l"(uh) : "l"(e.y), "l"(sh[2*j2+1])); \
            asm("fma.rn.f32x2 %0, %1, %2, %0;" : "+l"(vl) : "l"(o.x), "l"(dl[2*j2  ])); \
            asm("fma.rn.f32x2 %0, %1, %2, %0;" : "+l"(vh) : "l"(o.x), "l"(dh[2*j2  ])); \
            asm("fma.rn.f32x2 %0, %1, %2, %0;" : "+l"(vl) : "l"(o.y), "l"(dl[2*j2+1])); \
            asm("fma.rn.f32x2 %0, %1, %2, %0;" : "+l"(vh) : "l"(o.y), "l"(dh[2*j2+1])); \
        }                                                                               \
        longlong2 ya, yb;                                                               \
        unsigned long long w0, w1;                                                      \
        asm("add.rn.f32x2 %0, %1, %2;" : "=l"(w0) : "l"(ul), "l"(vl));                  \
        asm("add.rn.f32x2 %0, %1, %2;" : "=l"(w1) : "l"(uh), "l"(vh));                  \
        ya.x = (long long)w0; ya.y = (long long)w1;                                     \
        asm("fma.rn.f32x2 %0, %1, %2, %3;" : "=l"(w0) : "l"(NEG1), "l"(vl), "l"(ul));   \
        asm("fma.rn.f32x2 %0, %1, %2, %3;" : "=l"(w1) : "l"(NEG1), "l"(vh), "l"(uh));   \
        yb.x = (long long)w0; yb.y = (long long)w1;                                     \
        __stcs(out + base + (size_t)t * HW4 + (uu), ya);                                \
        __stcs(out + base + (size_t)(15 - t) * HW4 + (uu), yb);                         \
    }

    // ================= chunk 0 =================
    FOLD8();

    // half-depth prefetch of chunk 1 (4 pairs) -- x regs are dead, reuse them
    const int u1 = u0 + 256;
    #pragma unroll
    for (int j = 0; j < 4; j++) {
        xa[j] = __ldcs(r + base + (size_t)j * HW4 + u1);
        xb[j] = __ldcs(r + base + (size_t)(15 - j) * HW4 + u1);
    }

    MATVEC_STORE(u0);

    // remaining 4 pairs of chunk 1
    #pragma unroll
    for (int j = 4; j < 8; j++) {
        xa[j] = __ldcs(r + base + (size_t)j * HW4 + u1);
        xb[j] = __ldcs(r + base + (size_t)(15 - j) * HW4 + u1);
    }

    // ================= chunk 1 =================
    FOLD8();
    MATVEC_STORE(u1);

#undef FOLD8
#undef MATVEC_STORE
}

// ---------------------------------------------------------------------------
extern "C" void kernel_launch(void* const* d_in, const int* in_sizes, int n_in,
                              void* d_out, int out_size)
{
    const float* r  = (const float*)d_in[0];   // (8,64,16,64,64)
    const float* E  = (const float*)d_in[1];   // (8,768)
    const float* Wf = (const float*)d_in[2];   // (1024,768)
    const float* bf = (const float*)d_in[3];   // (1024,)
    float* out = (float*)d_out;

    dim3 grid(NBC, 2);
    fused_kernel<<<grid, 256>>>((const longlong2*)r,
                                (const float4*)E,
                                (const float4*)Wf,
                                bf,
                                (longlong2*)out);
}

// round 10
// speedup vs baseline: 1.1108x; 1.1108x over previous
#include <cuda_runtime.h>
#include <math.h>

// Problem shape (fixed): B=8, C=64, T=16, H=64, W=64, text_dim=768
#define NB 8
#define NC 64
#define NT 16
#define HW4 1024         // H*W/4 (float4 / longlong2 units per T-plane)
#define TD 768
#define NBC (NB*NC)      // 512

__device__ __forceinline__ unsigned long long pack2(float v) {
    float2 f = make_float2(v, v);
    return *reinterpret_cast<unsigned long long*>(&f);
}

// ---------------------------------------------------------------------------
// Single fused kernel.  Grid (512, 2); 256 threads; TWO sequential 256-column
// chunks per block (halves redundant Wf gate traffic vs grid (512,4)).
// NO cross-chunk register prefetch (R9's spill trigger): chunk-1 loads reuse
// the dead xa/xb registers after chunk-0's stores.  Prologue = R8's proven
// shape (chunk-0 loads -> gates in the load shadow -> E/O build), with E
// staged in smem so gates cost 12 Wf LDG.128/thread instead of 24.
// Per-chunk math identical to R6:  s=x[j]+x[15-j], d=x[j]-x[15-j];
// u=E s, v=O d;  y[t]=u+v, y[15-t]=u-v.
// ---------------------------------------------------------------------------
__global__ __launch_bounds__(256, 2) void fused_kernel(
    const longlong2* __restrict__ r,    // float4 planes as 2x f32x2
    const float4*    __restrict__ E4,   // (B, 768) as float4
    const float4*    __restrict__ Wf4,  // (C*T, 768) as float4
    const float*     __restrict__ bf,   // (C*T,)
    longlong2*       __restrict__ out)
{
    __shared__ float4 sE4[TD / 4];             // 3 KB: this batch's E row
    __shared__ float sw[NT];
    __shared__ float sD[NT][NT];
    __shared__ unsigned long long sEm[8][8];   // duplicated (m,m) pairs
    __shared__ unsigned long long sOm[8][8];

    const int bc = blockIdx.x;
    const int b  = bc >> 6;
    const int c  = bc & 63;
    const int u0 = blockIdx.y * 512 + threadIdx.x;   // chunk0 col; chunk1 = +256
    const size_t base = (size_t)bc * (NT * HW4);

    // ---- chunk-0 front-batched streaming DRAM loads (MLP=16), pairwise ----
    longlong2 xa[8], xb[8];
    #pragma unroll
    for (int j = 0; j < 8; j++) {
        xa[j] = __ldcs(r + base + (size_t)j * HW4 + u0);
        xb[j] = __ldcs(r + base + (size_t)(15 - j) * HW4 + u0);
    }

    // ---- DCT table + E staging (no deps on the loads) ----
    {
        const int k = threadIdx.x >> 4;
        const int t = threadIdx.x & 15;
        const float sc = (k == 0) ? 0.25f : 0.35355339059327373f; // sqrt(1/16), sqrt(2/16)
        sD[k][t] = cosf(3.14159265358979323846f * ((float)t + 0.5f) * (float)k / 16.0f) * sc;
    }
    if (threadIdx.x < TD / 4)
        sE4[threadIdx.x] = __ldg(E4 + (size_t)b * (TD / 4) + threadIdx.x);
    __syncthreads();

    // ---- gates in the load shadow: 16 groups x 16 lanes, one 768-dot ----
    {
        const int g = threadIdx.x >> 4;
        const int l = threadIdx.x & 15;
        const int j = c * NT + g;
        const float4* wrow = Wf4 + (size_t)j * (TD / 4);
        float s = 0.0f;
        #pragma unroll
        for (int i = 0; i < 12; i++) {
            const float4 wv = __ldg(wrow + l + 16 * i);   // L2-resident after wave 1
            const float4 ev = sE4[l + 16 * i];
            s = fmaf(ev.x, wv.x, s);
            s = fmaf(ev.y, wv.y, s);
            s = fmaf(ev.z, wv.z, s);
            s = fmaf(ev.w, wv.w, s);
        }
        #pragma unroll
        for (int o = 8; o; o >>= 1) s += __shfl_xor_sync(0xffffffffu, s, o);
        if (l == 0) {
            const float z = s + __ldg(bf + j);
            sw[g] = 1.0f / (1.0f + expf(-z));
        }
    }
    __syncthreads();

    // ---- folded matrices E (even k) / O (odd k), 8x8 each ----
    if (threadIdx.x < 128) {
        const int t   = (threadIdx.x >> 3) & 7;
        const int jj  = threadIdx.x & 7;
        const int odd = threadIdx.x >> 6;    // 0 -> Em, 1 -> Om
        float acc = 0.0f;
        #pragma unroll
        for (int m = 0; m < 8; m++) {
            const int k = 2 * m + odd;
            acc = fmaf(sD[k][t] * sw[k], sD[k][jj], acc);
        }
        const unsigned long long p = pack2(acc);
        if (odd) sOm[t][jj] = p; else sEm[t][jj] = p;
    }
    __syncthreads();

    const unsigned long long NEG1 = pack2(-1.0f);
    unsigned long long sl[8], sh[8], dl[8], dh[8];

// fold xa/xb -> sl/sh/dl/dh (x regs die here)
#define FOLD8()                                                                         \
    _Pragma("unroll")                                                                   \
    for (int j = 0; j < 8; j++) {                                                       \
        const unsigned long long al = (unsigned long long)xa[j].x;                      \
        const unsigned long long ah = (unsigned long long)xa[j].y;                      \
        const unsigned long long bl = (unsigned long long)xb[j].x;                      \
        const unsigned long long bh = (unsigned long long)xb[j].y;                      \
        asm("add.rn.f32x2 %0, %1, %2;"     : "=l"(sl[j]) : "l"(al), "l"(bl));           \
        asm("add.rn.f32x2 %0, %1, %2;"     : "=l"(sh[j]) : "l"(ah), "l"(bh));           \
        asm("fma.rn.f32x2 %0, %1, %2, %3;" : "=l"(dl[j]) : "l"(NEG1), "l"(bl), "l"(al));\
        asm("fma.rn.f32x2 %0, %1, %2, %3;" : "=l"(dh[j]) : "l"(NEG1), "l"(bh), "l"(ah));\
    }

// u = Em[t]·s, v = Om[t]·d; y[t]=u+v, y[15-t]=u-v; streamed stores at column uu
#define MATVEC_STORE(uu)                                                                \
    _Pragma("unroll")                                                                   \
    for (int t = 0; t < 8; t++) {                                                       \
        unsigned long long ul = 0ull, uh = 0ull, vl = 0ull, vh = 0ull;                  \
        _Pragma("unroll")                                                               \
        for (int j2 = 0; j2 < 4; j2++) {                                                \
            const ulonglong2 e = *(const ulonglong2*)&sEm[t][2 * j2];                   \
            const ulonglong2 o = *(const ulonglong2*)&sOm[t][2 * j2];                   \
            asm("fma.rn.f32x2 %0, %1, %2, %0;" : "+l"(ul) : "l"(e.x), "l"(sl[2*j2  ])); \
            asm("fma.rn.f32x2 %0, %1, %2, %0;" : "+l"(uh) : "l"(e.x), "l"(sh[2*j2  ])); \
            asm("fma.rn.f32x2 %0, %1, %2, %0;" : "+l"(ul) : "l"(e.y), "l"(sl[2*j2+1])); \
            asm("fma.rn.f32x2 %0, %1, %2, %0;" : "+l"(uh) : "l"(e.y), "l"(sh[2*j2+1])); \
            asm("fma.rn.f32x2 %0, %1, %2, %0;" : "+l"(vl) : "l"(o.x), "l"(dl[2*j2  ])); \
            asm("fma.rn.f32x2 %0, %1, %2, %0;" : "+l"(vh) : "l"(o.x), "l"(dh[2*j2  ])); \
            asm("fma.rn.f32x2 %0, %1, %2, %0;" : "+l"(vl) : "l"(o.y), "l"(dl[2*j2+1])); \
            asm("fma.rn.f32x2 %0, %1, %2, %0;" : "+l"(vh) : "l"(o.y), "l"(dh[2*j2+1])); \
        }                                                                               \
        longlong2 ya, yb;                                                               \
        unsigned long long w0, w1;                                                      \
        asm("add.rn.f32x2 %0, %1, %2;" : "=l"(w0) : "l"(ul), "l"(vl));                  \
        asm("add.rn.f32x2 %0, %1, %2;" : "=l"(w1) : "l"(uh), "l"(vh));                  \
        ya.x = (long long)w0; ya.y = (long long)w1;                                     \
        asm("fma.rn.f32x2 %0, %1, %2, %3;" : "=l"(w0) : "l"(NEG1), "l"(vl), "l"(ul));   \
        asm("fma.rn.f32x2 %0, %1, %2, %3;" : "=l"(w1) : "l"(NEG1), "l"(vh), "l"(uh));   \
        yb.x = (long long)w0; yb.y = (long long)w1;                                     \
        __stcs(out + base + (size_t)t * HW4 + (uu), ya);                                \
        __stcs(out + base + (size_t)(15 - t) * HW4 + (uu), yb);                         \
    }

    // ================= chunk 0 =================
    FOLD8();
    MATVEC_STORE(u0);

    // ================= chunk 1 (loads reuse dead xa/xb regs) =================
    const int u1 = u0 + 256;
    #pragma unroll
    for (int j = 0; j < 8; j++) {
        xa[j] = __ldcs(r + base + (size_t)j * HW4 + u1);
        xb[j] = __ldcs(r + base + (size_t)(15 - j) * HW4 + u1);
    }
    FOLD8();
    MATVEC_STORE(u1);

#undef FOLD8
#undef MATVEC_STORE
}

// ---------------------------------------------------------------------------
extern "C" void kernel_launch(void* const* d_in, const int* in_sizes, int n_in,
                              void* d_out, int out_size)
{
    const float* r  = (const float*)d_in[0];   // (8,64,16,64,64)
    const float* E  = (const float*)d_in[1];   // (8,768)
    const float* Wf = (const float*)d_in[2];   // (1024,768)
    const float* bf = (const float*)d_in[3];   // (1024,)
    float* out = (float*)d_out;

    dim3 grid(NBC, 2);
    fused_kernel<<<grid, 256>>>((const longlong2*)r,
                                (const float4*)E,
                                (const float4*)Wf,
                                bf,
                                (longlong2*)out);
}

// round 11
// speedup vs baseline: 2.4546x; 2.2098x over previous
#include <cuda_runtime.h>
#include <math.h>

// Problem shape (fixed): B=8, C=64, T=16, H=64, W=64, text_dim=768
#define NB 8
#define NC 64
#define NT 16
#define HW4 1024         // H*W/4 (float4 / longlong2 units per T-plane)
#define TD 768
#define NBC (NB*NC)      // 512

// Per-(b,c,t) sigmoid gates
__device__ float g_w[NBC * NT];   // 32 KB

__device__ __forceinline__ unsigned long long pack2(float v) {
    float2 f = make_float2(v, v);
    return *reinterpret_cast<unsigned long long*>(&f);
}

// ---------------------------------------------------------------------------
// Kernel 1: gates, minimum-latency form.  One block per (b,c) (512 blocks ->
// full chip in wave 1).  16 groups x 16 lanes; each group: one 768-dot with
// 12 independent LDG.128 pairs (MLP=12), butterfly reduce, sigmoid, store.
// No smem, no syncthreads -> critical path ~ one memory round trip.
// ---------------------------------------------------------------------------
__global__ __launch_bounds__(256) void gate_kernel(
    const float4* __restrict__ E4,   // (B, 768) as float4
    const float4* __restrict__ Wf4,  // (C*T, 768) as float4
    const float*  __restrict__ bf)   // (C*T,)
{
    const int bc = blockIdx.x;
    const int b  = bc >> 6;
    const int c  = bc & 63;
    const int g  = threadIdx.x >> 4;     // dot index 0..15
    const int l  = threadIdx.x & 15;     // lane within group

    const int j = c * NT + g;
    const float4* wrow = Wf4 + (size_t)j * (TD / 4);
    const float4* erow = E4 + (size_t)b * (TD / 4);

    float s = 0.0f;
    #pragma unroll
    for (int i = 0; i < 12; i++) {
        const float4 wv = __ldg(wrow + l + 16 * i);
        const float4 ev = __ldg(erow + l + 16 * i);
        s = fmaf(ev.x, wv.x, s);
        s = fmaf(ev.y, wv.y, s);
        s = fmaf(ev.z, wv.z, s);
        s = fmaf(ev.w, wv.w, s);
    }
    #pragma unroll
    for (int o = 8; o; o >>= 1) s += __shfl_xor_sync(0xffffffffu, s, o);
    if (l == 0) {
        const float z = s + __ldg(bf + j);
        g_w[bc * NT + g] = 1.0f / (1.0f + expf(-z));
    }
}

// ---------------------------------------------------------------------------
// Kernel 2: streaming modulation with even/odd folding — EXACT R6 shape
// (39.3us, 128 regs, no spill).  Grid (512, 4); 256 threads; float4 columns.
//   s=x[j]+x[15-j], d=x[j]-x[15-j];  u=E s, v=O d;  y[t]=u+v, y[15-t]=u-v.
// ---------------------------------------------------------------------------
__global__ __launch_bounds__(256, 2) void mod_kernel(
    const longlong2* __restrict__ r,    // float4 planes as 2x f32x2
    longlong2* __restrict__ out)
{
    __shared__ float sw[NT];
    __shared__ float sD[NT][NT];
    __shared__ unsigned long long sEm[8][8];   // duplicated (m,m) pairs
    __shared__ unsigned long long sOm[8][8];

    const int bc = blockIdx.x;
    const int u = blockIdx.y * 256 + threadIdx.x;        // [0, 1024)
    const size_t base = (size_t)bc * (NT * HW4) + u;

    // Front-batched streaming loads: 16 independent LDG.128 (MLP=16)
    longlong2 x[NT];
    #pragma unroll
    for (int k = 0; k < NT; k++)
        x[k] = __ldcs(r + base + (size_t)k * HW4);

    // ---- prologue (hidden under loads): gates + DCT table ----
    if (threadIdx.x < NT) sw[threadIdx.x] = g_w[bc * NT + threadIdx.x];
    {
        const int k = threadIdx.x >> 4;
        const int t = threadIdx.x & 15;
        const float sc = (k == 0) ? 0.25f : 0.35355339059327373f; // sqrt(1/16), sqrt(2/16)
        sD[k][t] = cosf(3.14159265358979323846f * ((float)t + 0.5f) * (float)k / 16.0f) * sc;
    }
    __syncthreads();
    if (threadIdx.x < 128) {
        const int t   = (threadIdx.x >> 3) & 7;
        const int jj  = threadIdx.x & 7;
        const int odd = threadIdx.x >> 6;    // 0 -> E, 1 -> O
        float acc = 0.0f;
        #pragma unroll
        for (int m = 0; m < 8; m++) {
            const int k = 2 * m + odd;
            acc = fmaf(sD[k][t] * sw[k], sD[k][jj], acc);
        }
        const unsigned long long p = pack2(acc);
        if (odd) sOm[t][jj] = p; else sEm[t][jj] = p;
    }

    // ---- fold: s/d (x dies here) ----
    const unsigned long long NEG1 = pack2(-1.0f);
    unsigned long long sl[8], sh[8], dl[8], dh[8];
    #pragma unroll
    for (int j = 0; j < 8; j++) {
        const unsigned long long al = (unsigned long long)x[j].x;
        const unsigned long long ah = (unsigned long long)x[j].y;
        const unsigned long long bl = (unsigned long long)x[15 - j].x;
        const unsigned long long bh = (unsigned long long)x[15 - j].y;
        asm("add.rn.f32x2 %0, %1, %2;"     : "=l"(sl[j]) : "l"(al), "l"(bl));
        asm("add.rn.f32x2 %0, %1, %2;"     : "=l"(sh[j]) : "l"(ah), "l"(bh));
        asm("fma.rn.f32x2 %0, %1, %2, %3;" : "=l"(dl[j]) : "l"(NEG1), "l"(bl), "l"(al));
        asm("fma.rn.f32x2 %0, %1, %2, %3;" : "=l"(dh[j]) : "l"(NEG1), "l"(bh), "l"(ah));
    }
    __syncthreads();

    // ---- 8 folded rows: u = E[t]·s, v = O[t]·d ----
    #pragma unroll
    for (int t = 0; t < 8; t++) {
        unsigned long long ul = 0ull, uh = 0ull, vl = 0ull, vh = 0ull;
        #pragma unroll
        for (int j2 = 0; j2 < 4; j2++) {
            const ulonglong2 e = *(const ulonglong2*)&sEm[t][2 * j2];  // LDS.128
            const ulonglong2 o = *(const ulonglong2*)&sOm[t][2 * j2];  // LDS.128
            asm("fma.rn.f32x2 %0, %1, %2, %0;" : "+l"(ul) : "l"(e.x), "l"(sl[2*j2  ]));
            asm("fma.rn.f32x2 %0, %1, %2, %0;" : "+l"(uh) : "l"(e.x), "l"(sh[2*j2  ]));
            asm("fma.rn.f32x2 %0, %1, %2, %0;" : "+l"(ul) : "l"(e.y), "l"(sl[2*j2+1]));
            asm("fma.rn.f32x2 %0, %1, %2, %0;" : "+l"(uh) : "l"(e.y), "l"(sh[2*j2+1]));
            asm("fma.rn.f32x2 %0, %1, %2, %0;" : "+l"(vl) : "l"(o.x), "l"(dl[2*j2  ]));
            asm("fma.rn.f32x2 %0, %1, %2, %0;" : "+l"(vh) : "l"(o.x), "l"(dh[2*j2  ]));
            asm("fma.rn.f32x2 %0, %1, %2, %0;" : "+l"(vl) : "l"(o.y), "l"(dl[2*j2+1]));
            asm("fma.rn.f32x2 %0, %1, %2, %0;" : "+l"(vh) : "l"(o.y), "l"(dh[2*j2+1]));
        }
        longlong2 ya, yb;
        unsigned long long w0, w1;
        asm("add.rn.f32x2 %0, %1, %2;" : "=l"(w0) : "l"(ul), "l"(vl));
        asm("add.rn.f32x2 %0, %1, %2;" : "=l"(w1) : "l"(uh), "l"(vh));
        ya.x = (long long)w0; ya.y = (long long)w1;
        asm("fma.rn.f32x2 %0, %1, %2, %3;" : "=l"(w0) : "l"(NEG1), "l"(vl), "l"(ul));
        asm("fma.rn.f32x2 %0, %1, %2, %3;" : "=l"(w1) : "l"(NEG1), "l"(vh), "l"(uh));
        yb.x = (long long)w0; yb.y = (long long)w1;
        __stcs(out + base + (size_t)t * HW4, ya);
        __stcs(out + base + (size_t)(15 - t) * HW4, yb);
    }
}

// ---------------------------------------------------------------------------
extern "C" void kernel_launch(void* const* d_in, const int* in_sizes, int n_in,
                              void* d_out, int out_size)
{
    const float* r  = (const float*)d_in[0];   // (8,64,16,64,64)
    const float* E  = (const float*)d_in[1];   // (8,768)
    const float* Wf = (const float*)d_in[2];   // (1024,768)
    const float* bf = (const float*)d_in[3];   // (1024,)
    float* out = (float*)d_out;

    gate_kernel<<<NBC, 256>>>((const float4*)E, (const float4*)Wf, bf);

    dim3 grid(NBC, 4);
    mod_kernel<<<grid, 256>>>((const longlong2*)r, (longlong2*)out);
}